// round 3
// baseline (speedup 1.0000x reference)
#include <cuda_runtime.h>

// Rx(theta) on target qubit = MSB of the state index.
// Inputs:  d_in[0] = state_re (2^24 f32), d_in[1] = state_im (2^24 f32),
//          d_in[2] = theta (1 f32)
// Output:  d_out = [2, 2^24] f32  (out[0,:] = real, out[1,:] = imag)
//
// Pairing: k in [0, 2^23) pairs with k + 2^23 (h = 2^23).
//   c = cos(theta/2), s = sin(theta/2)
//   out0 = c*a - i*s*b ; out1 = -i*s*a + c*b   (a = psi[k], b = psi[k+h])
//
//   out_re[k]   =  c*a_re + s*b_im     out_im[k]   =  c*a_im - s*b_re
//   out_re[k+h] =  s*a_im + c*b_re     out_im[k+h] = -s*a_re + c*b_im

__global__ __launch_bounds__(256) void rx_gate_kernel(
    const float* __restrict__ re,
    const float* __restrict__ im,
    const float* __restrict__ theta,
    float* __restrict__ out_re,
    float* __restrict__ out_im,
    int half)
{
    int k = (blockIdx.x * blockDim.x + threadIdx.x) * 4;
    if (k >= half) return;

    float c, s;
    sincosf(0.5f * __ldg(theta), &s, &c);

    const float4 a_re = __ldg(reinterpret_cast<const float4*>(re + k));
    const float4 a_im = __ldg(reinterpret_cast<const float4*>(im + k));
    const float4 b_re = __ldg(reinterpret_cast<const float4*>(re + half + k));
    const float4 b_im = __ldg(reinterpret_cast<const float4*>(im + half + k));

    float4 o0re, o0im, o1re, o1im;

    o0re.x = fmaf(c, a_re.x,  s * b_im.x);
    o0re.y = fmaf(c, a_re.y,  s * b_im.y);
    o0re.z = fmaf(c, a_re.z,  s * b_im.z);
    o0re.w = fmaf(c, a_re.w,  s * b_im.w);

    o0im.x = fmaf(c, a_im.x, -s * b_re.x);
    o0im.y = fmaf(c, a_im.y, -s * b_re.y);
    o0im.z = fmaf(c, a_im.z, -s * b_re.z);
    o0im.w = fmaf(c, a_im.w, -s * b_re.w);

    o1re.x = fmaf(c, b_re.x,  s * a_im.x);
    o1re.y = fmaf(c, b_re.y,  s * a_im.y);
    o1re.z = fmaf(c, b_re.z,  s * a_im.z);
    o1re.w = fmaf(c, b_re.w,  s * a_im.w);

    o1im.x = fmaf(c, b_im.x, -s * a_re.x);
    o1im.y = fmaf(c, b_im.y, -s * a_re.y);
    o1im.z = fmaf(c, b_im.z, -s * a_re.z);
    o1im.w = fmaf(c, b_im.w, -s * a_re.w);

    *reinterpret_cast<float4*>(out_re + k)        = o0re;
    *reinterpret_cast<float4*>(out_im + k)        = o0im;
    *reinterpret_cast<float4*>(out_re + half + k) = o1re;
    *reinterpret_cast<float4*>(out_im + half + k) = o1im;
}

extern "C" void kernel_launch(void* const* d_in, const int* in_sizes, int n_in,
                              void* d_out, int out_size) {
    const float* re    = (const float*)d_in[0];
    const float* im    = (const float*)d_in[1];
    const float* theta = (const float*)d_in[2];

    const int n    = in_sizes[0];       // 2^24
    const int half = n >> 1;            // 2^23

    float* out_re = (float*)d_out;      // out[0, :]
    float* out_im = (float*)d_out + n;  // out[1, :]

    const int threads = 256;
    const int blocks  = (half / 4 + threads - 1) / threads;  // 8192
    rx_gate_kernel<<<blocks, threads>>>(re, im, theta, out_re, out_im, half);
}

// round 5
// speedup vs baseline: 1.0129x; 1.0129x over previous
#include <cuda_runtime.h>

// Rx(theta) on target qubit = MSB of the state index.
// Inputs:  d_in[0] = state_re (2^24 f32), d_in[1] = state_im (2^24 f32),
//          d_in[2] = theta (1 f32)
// Output:  d_out = [2, 2^24] f32  (out[0,:] = real, out[1,:] = imag)
//
// Pairing: k in [0, 2^23) pairs with k + 2^23 (h = 2^23).
//   c = cos(theta/2), s = sin(theta/2)
//   out_re[k]   =  c*a_re + s*b_im     out_im[k]   =  c*a_im - s*b_re
//   out_re[k+h] =  s*a_im + c*b_re     out_im[k+h] = -s*a_re + c*b_im
//
// Zero-reuse streaming kernel: all loads/stores use evict-streaming (.cs)
// cache hints so the 256 MB of one-shot traffic doesn't thrash L2.

__global__ __launch_bounds__(256) void rx_gate_kernel(
    const float* __restrict__ re,
    const float* __restrict__ im,
    const float* __restrict__ theta,
    float* __restrict__ out_re,
    float* __restrict__ out_im,
    int half)
{
    int k = (blockIdx.x * blockDim.x + threadIdx.x) * 4;
    if (k >= half) return;

    float c, s;
    sincosf(0.5f * __ldg(theta), &s, &c);

    const float4 a_re = __ldcs(reinterpret_cast<const float4*>(re + k));
    const float4 a_im = __ldcs(reinterpret_cast<const float4*>(im + k));
    const float4 b_re = __ldcs(reinterpret_cast<const float4*>(re + half + k));
    const float4 b_im = __ldcs(reinterpret_cast<const float4*>(im + half + k));

    float4 o0re, o0im, o1re, o1im;

    o0re.x = fmaf(c, a_re.x,  s * b_im.x);
    o0re.y = fmaf(c, a_re.y,  s * b_im.y);
    o0re.z = fmaf(c, a_re.z,  s * b_im.z);
    o0re.w = fmaf(c, a_re.w,  s * b_im.w);

    o0im.x = fmaf(c, a_im.x, -s * b_re.x);
    o0im.y = fmaf(c, a_im.y, -s * b_re.y);
    o0im.z = fmaf(c, a_im.z, -s * b_re.z);
    o0im.w = fmaf(c, a_im.w, -s * b_re.w);

    o1re.x = fmaf(c, b_re.x,  s * a_im.x);
    o1re.y = fmaf(c, b_re.y,  s * a_im.y);
    o1re.z = fmaf(c, b_re.z,  s * a_im.z);
    o1re.w = fmaf(c, b_re.w,  s * a_im.w);

    o1im.x = fmaf(c, b_im.x, -s * a_re.x);
    o1im.y = fmaf(c, b_im.y, -s * a_re.y);
    o1im.z = fmaf(c, b_im.z, -s * a_re.z);
    o1im.w = fmaf(c, b_im.w, -s * a_re.w);

    __stcs(reinterpret_cast<float4*>(out_re + k),        o0re);
    __stcs(reinterpret_cast<float4*>(out_im + k),        o0im);
    __stcs(reinterpret_cast<float4*>(out_re + half + k), o1re);
    __stcs(reinterpret_cast<float4*>(out_im + half + k), o1im);
}

extern "C" void kernel_launch(void* const* d_in, const int* in_sizes, int n_in,
                              void* d_out, int out_size) {
    const float* re    = (const float*)d_in[0];
    const float* im    = (const float*)d_in[1];
    const float* theta = (const float*)d_in[2];

    const int n    = in_sizes[0];       // 2^24
    const int half = n >> 1;            // 2^23

    float* out_re = (float*)d_out;      // out[0, :]
    float* out_im = (float*)d_out + n;  // out[1, :]

    const int threads = 256;
    const int blocks  = (half / 4 + threads - 1) / threads;  // 8192
    rx_gate_kernel<<<blocks, threads>>>(re, im, theta, out_re, out_im, half);
}